// round 6
// baseline (speedup 1.0000x reference)
#include <cuda_runtime.h>
#include <cuda_bf16.h>

// ---------------------------------------------------------------------------
// Transformer-XL relative multi-head attention + residual + LayerNorm (fp32)
// GEMMs run on the tensor pipe via bf16 hi/lo split (3 MMAs ~ fp32 accuracy):
//   a = hi + lo,  hi = bf16(a), lo = bf16(a - hi)
//   a*b ~= hi*hi' + hi*lo' + lo*hi'      (lo*lo' ~ 2^-18 |ab|, dropped)
// Each bf16 product is exact in fp32; accumulation is fp32.
//
// Smem tiles use a padded row stride of 24 bf16 (48 B = 12 banks) so the
// fragment loads (bank = (12*g + tig) mod 32) are conflict-free.
//
// rel_shift closed form (I=1024 queries, J=2048 keys), e = j - i + 1023:
//   e <  2048 : BD(i,j) = raw[i, e]
//   e == 2048 : BD(i,j) = 0
//   e >  2048 : BD(i,j) = raw[i+1, e-2049]     (wrap into next query row)
// where raw = (Q + pos_bias_v) @ R^T per (b, head).  Wrap requires i <= 1021,
// so the i+1 access is always in bounds.
// ---------------------------------------------------------------------------

namespace {
constexpr int S    = 1024;   // query length
constexpr int MEMN = 1024;   // memory length
constexpr int T    = 2048;   // total key length
constexpr int B    = 4;      // batch
constexpr int D    = 1024;   // d_model
constexpr int NH   = 16;     // heads
constexpr int HD   = 64;     // head dim
constexpr int N3   = 3072;   // 3 * NH * HD
}

// Scratch (device globals are the sanctioned scratch mechanism)
__device__ float g_q [(size_t)B * NH * S * HD];   //  16 MB  [b][n][i][d]
__device__ float g_k [(size_t)B * NH * T * HD];   //  32 MB  [b][n][t][d]
__device__ float g_v [(size_t)B * NH * T * HD];   //  32 MB
__device__ float g_r [(size_t)B * NH * T * HD];   //  32 MB
__device__ float g_bd[(size_t)B * NH * S * T];    // 512 MB  raw BD matrix
__device__ float g_sc[(size_t)B * NH * S * T];    // 512 MB  scores / probs
__device__ float g_av[(size_t)S * B * D];         //  16 MB  attn_vec [i][b][h]

// one m16n8k16 bf16 MMA, fp32 accumulate
__device__ __forceinline__ void mma16816(float* c, const unsigned* a, const unsigned* b)
{
    asm volatile(
        "mma.sync.aligned.m16n8k16.row.col.f32.bf16.bf16.f32 "
        "{%0,%1,%2,%3}, {%4,%5,%6,%7}, {%8,%9}, {%0,%1,%2,%3};\n"
        : "+f"(c[0]), "+f"(c[1]), "+f"(c[2]), "+f"(c[3])
        : "r"(a[0]), "r"(a[1]), "r"(a[2]), "r"(a[3]), "r"(b[0]), "r"(b[1]));
}

// split two floats into (hi, lo) bf16 pairs, packed for 32-bit smem stores
__device__ __forceinline__ void split2(float v0, float v1,
                                       __nv_bfloat162& h2, __nv_bfloat162& l2)
{
    h2 = __floats2bfloat162_rn(v0, v1);
    l2 = __floats2bfloat162_rn(v0 - __bfloat162float(h2.x),
                               v1 - __bfloat162float(h2.y));
}

// ---------------------------------------------------------------------------
// Generic NT GEMM on tensor pipe: C[m,n] = sum_k A[m,k] * Bmat[n,k]
// 128x128 tile, BK=16 (row stride 24), 256 threads (8 warps 2x4), dbl-buffered.
// MODE 0: QKV projection (A = concat(memory,x)), scatter into g_q/g_k/g_v
// MODE 1: REL projection (A = pos_emb), scatter into g_r
// MODE 2: BDraw = (Q + pos_bias_v) @ R^T  per (b,n)  -> g_bd
// MODE 3: scores = scale*((Q+u)@K^T + shift(BDraw))  per (b,n) -> g_sc
// MODE 5: out-proj = AV @ W_o^T + x -> d_out
// ---------------------------------------------------------------------------
template <int MODE>
__global__ __launch_bounds__(256, 2)
void gemm_nt(const float* __restrict__ Aa, const float* __restrict__ Ab,
             const float* __restrict__ Bm, const float* __restrict__ biasbase,
             const float* __restrict__ aux, float* __restrict__ Cout,
             int M, int N, int K)
{
    constexpr int BM = 128, BNT = 128, BK = 16, BKP = 24; // padded stride
    __shared__ alignas(16) __nv_bfloat16 sAh[2][BM][BKP];
    __shared__ alignas(16) __nv_bfloat16 sAl[2][BM][BKP];
    __shared__ alignas(16) __nv_bfloat16 sBh[2][BNT][BKP];
    __shared__ alignas(16) __nv_bfloat16 sBl[2][BNT][BKP];

    const int tid  = threadIdx.x;
    const int m0   = blockIdx.y * BM;
    const int n0   = blockIdx.x * BNT;
    const int z    = blockIdx.z;          // (b*16 + n) for MODE 2/3
    const int warp = tid >> 5;
    const int lane = tid & 31;
    const int g    = lane >> 2;           // 0..7
    const int tig  = lane & 3;            // 0..3
    const int wm0  = (warp >> 2) * 64;    // 2 warp rows
    const int wn0  = (warp & 3) * 32;     // 4 warp cols

    // Dead tiles: q-outputs for memory rows are discarded -> skip whole block.
    if constexpr (MODE == 0) {
        if (blockIdx.x < 8 && blockIdx.y < 32) return;
    }

    const float* bias = nullptr;
    if constexpr (MODE == 2 || MODE == 3) bias = biasbase + (z & 15) * HD;

    float acc[4][4][4];
#pragma unroll
    for (int i = 0; i < 4; i++)
#pragma unroll
        for (int j = 0; j < 4; j++)
#pragma unroll
            for (int c = 0; c < 4; c++) acc[i][j][c] = 0.f;

    float4 pa[2], pb[2];

    auto loadA = [&](int k0) {
#pragma unroll
        for (int it = 0; it < 2; it++) {
            int idx  = tid * 2 + it;
            int row  = idx >> 2;
            int ks   = (idx & 3) << 2;
            int mrow = m0 + row;
            const float* ap;
            if constexpr (MODE == 0)
                ap = (mrow < MEMN * B) ? Aa + (size_t)mrow * D
                                       : Ab + (size_t)(mrow - MEMN * B) * D;
            else if constexpr (MODE == 1)
                ap = Aa + (size_t)mrow * D;
            else if constexpr (MODE == 2 || MODE == 3)
                ap = g_q + ((size_t)z * S + mrow) * HD;
            else
                ap = g_av + (size_t)mrow * D;
            float4 v = *(const float4*)(ap + k0 + ks);
            if constexpr (MODE == 2 || MODE == 3) {
                v.x += bias[k0 + ks + 0];
                v.y += bias[k0 + ks + 1];
                v.z += bias[k0 + ks + 2];
                v.w += bias[k0 + ks + 3];
            }
            pa[it] = v;
        }
    };
    auto loadB = [&](int k0) {
#pragma unroll
        for (int it = 0; it < 2; it++) {
            int idx  = tid * 2 + it;
            int row  = idx >> 2;
            int ks   = (idx & 3) << 2;
            int nrow = n0 + row;
            const float* bp;
            if constexpr (MODE == 2)
                bp = g_r + ((size_t)z * T + nrow) * HD;
            else if constexpr (MODE == 3)
                bp = g_k + ((size_t)z * T + nrow) * HD;
            else
                bp = Bm + (size_t)nrow * K;
            pb[it] = *(const float4*)(bp + k0 + ks);
        }
    };
    auto stash = [&](int buf) {
#pragma unroll
        for (int it = 0; it < 2; it++) {
            int idx = tid * 2 + it;
            int row = idx >> 2;
            int ks  = (idx & 3) << 2;
            const float av[4] = { pa[it].x, pa[it].y, pa[it].z, pa[it].w };
            const float bv[4] = { pb[it].x, pb[it].y, pb[it].z, pb[it].w };
#pragma unroll
            for (int e = 0; e < 4; e += 2) {
                __nv_bfloat162 h2, l2;
                split2(av[e], av[e + 1], h2, l2);
                *(__nv_bfloat162*)&sAh[buf][row][ks + e] = h2;
                *(__nv_bfloat162*)&sAl[buf][row][ks + e] = l2;
                split2(bv[e], bv[e + 1], h2, l2);
                *(__nv_bfloat162*)&sBh[buf][row][ks + e] = h2;
                *(__nv_bfloat162*)&sBl[buf][row][ks + e] = l2;
            }
        }
    };

    auto ldAfrag = [&](unsigned A[4][4], const __nv_bfloat16 (*src)[BKP]) {
#pragma unroll
        for (int mf = 0; mf < 4; mf++) {
            int r = wm0 + mf * 16 + g;
            A[mf][0] = *(const unsigned*)&src[r    ][tig * 2    ];
            A[mf][1] = *(const unsigned*)&src[r + 8][tig * 2    ];
            A[mf][2] = *(const unsigned*)&src[r    ][tig * 2 + 8];
            A[mf][3] = *(const unsigned*)&src[r + 8][tig * 2 + 8];
        }
    };
    auto ldBfrag = [&](unsigned Bf[4][2], const __nv_bfloat16 (*src)[BKP]) {
#pragma unroll
        for (int nf = 0; nf < 4; nf++) {
            int r = wn0 + nf * 8 + g;
            Bf[nf][0] = *(const unsigned*)&src[r][tig * 2    ];
            Bf[nf][1] = *(const unsigned*)&src[r][tig * 2 + 8];
        }
    };
    auto domma = [&](const unsigned A[4][4], const unsigned Bf[4][2]) {
#pragma unroll
        for (int mf = 0; mf < 4; mf++)
#pragma unroll
            for (int nf = 0; nf < 4; nf++)
                mma16816(acc[mf][nf], A[mf], Bf[nf]);
    };

    loadA(0); loadB(0);
    stash(0);
    __syncthreads();

    int cur = 0;
    for (int k0 = 0; k0 < K; k0 += BK) {
        const bool has_next = (k0 + BK) < K;
        if (has_next) { loadA(k0 + BK); loadB(k0 + BK); }

        // Phase order chosen so B-hi is loaded once and stays live:
        //   hi*lo, hi*hi, lo*hi  -> 2 A-loads + 2 B-loads per k-step.
        unsigned Af[4][4], Bf[4][2];
        ldAfrag(Af, sAh[cur]);           // A hi
        ldBfrag(Bf, sBl[cur]);           // B lo
        domma(Af, Bf);                   // hi*lo
        ldBfrag(Bf, sBh[cur]);           // B hi
        domma(Af, Bf);                   // hi*hi
        ldAfrag(Af, sAl[cur]);           // A lo (B hi still live)
        domma(Af, Bf);                   // lo*hi

        if (has_next) {
            stash(cur ^ 1);
            __syncthreads();
            cur ^= 1;
        }
    }

    // ---- epilogue: acc[mf][nf][ci] -> (m, h) ----
#pragma unroll
    for (int mf = 0; mf < 4; mf++) {
#pragma unroll
        for (int nf = 0; nf < 4; nf++) {
#pragma unroll
            for (int ci = 0; ci < 4; ci++) {
                int m = m0 + wm0 + mf * 16 + g + ((ci >> 1) * 8);
                int h = n0 + wn0 + nf * 8 + tig * 2 + (ci & 1);
                float val = acc[mf][nf][ci];
                if constexpr (MODE == 0) {
                    int t  = m >> 2, bb = m & 3;
                    int sec = h >> 10, hh = h & 1023;
                    int n  = hh >> 6, dd = hh & 63;
                    if (sec == 0) {
                        if (t >= MEMN)
                            g_q[(((size_t)bb * NH + n) * S + (t - MEMN)) * HD + dd] = val;
                    } else if (sec == 1) {
                        g_k[(((size_t)bb * NH + n) * T + t) * HD + dd] = val;
                    } else {
                        g_v[(((size_t)bb * NH + n) * T + t) * HD + dd] = val;
                    }
                } else if constexpr (MODE == 1) {
                    int t = m >> 2, bb = m & 3;
                    int n = h >> 6, dd = h & 63;
                    g_r[(((size_t)bb * NH + n) * T + t) * HD + dd] = val;
                } else if constexpr (MODE == 2) {
                    g_bd[((size_t)z * S + m) * T + h] = val;
                } else if constexpr (MODE == 3) {
                    int e = h - m + (S - 1);
                    float bd;
                    if (e < T)       bd = g_bd[((size_t)z * S + m) * T + e];
                    else if (e == T) bd = 0.f;
                    else             bd = g_bd[((size_t)z * S + m + 1) * T + (e - T - 1)];
                    g_sc[((size_t)z * S + m) * T + h] = (val + bd) * 0.125f; // 1/sqrt(64)
                } else { // MODE 5: out-proj + residual
                    Cout[(size_t)m * D + h] = val + aux[(size_t)m * D + h];
                }
            }
        }
    }
}

// ---------------------------------------------------------------------------
// PV GEMM (NN): av[i,dd] = sum_j P[i,j] * V[j,dd] per (b,n).
// 128x64 tile on tensor pipe; V tile transposed into smem (k-contiguous).
// ---------------------------------------------------------------------------
__global__ __launch_bounds__(256, 2)
void gemm_pv()
{
    constexpr int BM = 128, BK = 16, BN = 64, BKP = 24; // padded stride
    __shared__ alignas(16) __nv_bfloat16 sAh[2][BM][BKP];
    __shared__ alignas(16) __nv_bfloat16 sAl[2][BM][BKP];
    __shared__ alignas(16) __nv_bfloat16 sVh[2][BN][BKP];
    __shared__ alignas(16) __nv_bfloat16 sVl[2][BN][BKP];

    const int tid  = threadIdx.x;
    const int m0   = blockIdx.y * BM;
    const int z    = blockIdx.z;
    const int warp = tid >> 5;
    const int lane = tid & 31;
    const int g    = lane >> 2;
    const int tig  = lane & 3;
    const int wm0  = (warp >> 2) * 64;
    const int wn0  = (warp & 3) * 16;

    const float* Ap = g_sc + (size_t)z * S * T;
    const float* Vp = g_v  + (size_t)z * T * HD;

    float acc[4][2][4];
#pragma unroll
    for (int i = 0; i < 4; i++)
#pragma unroll
        for (int j = 0; j < 2; j++)
#pragma unroll
            for (int c = 0; c < 4; c++) acc[i][j][c] = 0.f;

    float4 pa[2], pb;
    auto loadA = [&](int k0) {
#pragma unroll
        for (int it = 0; it < 2; it++) {
            int idx = tid * 2 + it;
            int row = idx >> 2;
            int ks  = (idx & 3) << 2;
            pa[it] = *(const float4*)(Ap + (size_t)(m0 + row) * T + k0 + ks);
        }
    };
    auto loadB = [&](int k0) {
        int row = tid >> 4;           // k within tile, 0..15
        int cs  = (tid & 15) << 2;    // dd, 0..60
        pb = *(const float4*)(Vp + (size_t)(k0 + row) * HD + cs);
    };
    auto stash = [&](int buf) {
#pragma unroll
        for (int it = 0; it < 2; it++) {
            int idx = tid * 2 + it;
            int row = idx >> 2;
            int ks  = (idx & 3) << 2;
            const float av[4] = { pa[it].x, pa[it].y, pa[it].z, pa[it].w };
#pragma unroll
            for (int e = 0; e < 4; e += 2) {
                __nv_bfloat162 h2, l2;
                split2(av[e], av[e + 1], h2, l2);
                *(__nv_bfloat162*)&sAh[buf][row][ks + e] = h2;
                *(__nv_bfloat162*)&sAl[buf][row][ks + e] = l2;
            }
        }
        int row = tid >> 4;           // k index
        int cs  = (tid & 15) << 2;    // dd base
        const float bv[4] = { pb.x, pb.y, pb.z, pb.w };
#pragma unroll
        for (int e = 0; e < 4; e++) { // transpose: [dd][k] (scalar, strided)
            __nv_bfloat16 h = __float2bfloat16(bv[e]);
            __nv_bfloat16 l = __float2bfloat16(bv[e] - __bfloat162float(h));
            sVh[buf][cs + e][row] = h;
            sVl[buf][cs + e][row] = l;
        }
    };

    auto ldAfrag = [&](unsigned A[4][4], const __nv_bfloat16 (*src)[BKP]) {
#pragma unroll
        for (int mf = 0; mf < 4; mf++) {
            int r = wm0 + mf * 16 + g;
            A[mf][0] = *(const unsigned*)&src[r    ][tig * 2    ];
            A[mf][1] = *(const unsigned*)&src[r + 8][tig * 2    ];
            A[mf][2] = *(const unsigned*)&src[r    ][tig * 2 + 8];
            A[mf][3] = *(const unsigned*)&src[r + 8][tig * 2 + 8];
        }
    };
    auto ldBfrag = [&](unsigned Bf[2][2], const __nv_bfloat16 (*src)[BKP]) {
#pragma unroll
        for (int nf = 0; nf < 2; nf++) {
            int r = wn0 + nf * 8 + g;
            Bf[nf][0] = *(const unsigned*)&src[r][tig * 2    ];
            Bf[nf][1] = *(const unsigned*)&src[r][tig * 2 + 8];
        }
    };
    auto domma = [&](const unsigned A[4][4], const unsigned Bf[2][2]) {
#pragma unroll
        for (int mf = 0; mf < 4; mf++)
#pragma unroll
            for (int nf = 0; nf < 2; nf++)
                mma16816(acc[mf][nf], A[mf], Bf[nf]);
    };

    loadA(0); loadB(0);
    stash(0);
    __syncthreads();

    int cur = 0;
    for (int k0 = 0; k0 < T; k0 += BK) {
        const bool has_next = (k0 + BK) < T;
        if (has_next) { loadA(k0 + BK); loadB(k0 + BK); }

        unsigned Af[4][4], Bf[2][2];
        ldAfrag(Af, sAh[cur]);       // A hi
        ldBfrag(Bf, sVl[cur]);       // V lo
        domma(Af, Bf);               // hi*lo
        ldBfrag(Bf, sVh[cur]);       // V hi
        domma(Af, Bf);               // hi*hi
        ldAfrag(Af, sAl[cur]);       // A lo (V hi still live)
        domma(Af, Bf);               // lo*hi

        if (has_next) {
            stash(cur ^ 1);
            __syncthreads();
            cur ^= 1;
        }
    }

    const int bb = z >> 4, n = z & 15;
#pragma unroll
    for (int mf = 0; mf < 4; mf++) {
#pragma unroll
        for (int nf = 0; nf < 2; nf++) {
#pragma unroll
            for (int ci = 0; ci < 4; ci++) {
                int irow = m0 + wm0 + mf * 16 + g + ((ci >> 1) * 8);
                int dd   = wn0 + nf * 8 + tig * 2 + (ci & 1);
                g_av[((size_t)irow * B + bb) * D + n * HD + dd] = acc[mf][nf][ci];
            }
        }
    }
}

// ---------------------------------------------------------------------------
// Block reductions (256 threads)
// ---------------------------------------------------------------------------
__device__ __forceinline__ float blk_sum(float v, float* sred, int tid)
{
#pragma unroll
    for (int o = 16; o; o >>= 1) v += __shfl_xor_sync(0xffffffffu, v, o);
    if ((tid & 31) == 0) sred[tid >> 5] = v;
    __syncthreads();
    float r = 0.f;
#pragma unroll
    for (int w = 0; w < 8; w++) r += sred[w];
    __syncthreads();
    return r;
}

__device__ __forceinline__ float blk_max(float v, float* sred, int tid)
{
#pragma unroll
    for (int o = 16; o; o >>= 1) v = fmaxf(v, __shfl_xor_sync(0xffffffffu, v, o));
    if ((tid & 31) == 0) sred[tid >> 5] = v;
    __syncthreads();
    float r = sred[0];
#pragma unroll
    for (int w = 1; w < 8; w++) r = fmaxf(r, sred[w]);
    __syncthreads();
    return r;
}

// Softmax over the key dim (2048) — one block per (b,n,i) row, in place.
__global__ __launch_bounds__(256, 4)
void softmax_k()
{
    __shared__ float sred[8];
    float* p = g_sc + (size_t)blockIdx.x * T;
    const int tid = threadIdx.x;
    float v[8];
    float mx = -1e30f;
#pragma unroll
    for (int i = 0; i < 8; i++) { v[i] = p[tid + i * 256]; mx = fmaxf(mx, v[i]); }
    mx = blk_max(mx, sred, tid);
    float s = 0.f;
#pragma unroll
    for (int i = 0; i < 8; i++) { v[i] = __expf(v[i] - mx); s += v[i]; }
    s = blk_sum(s, sred, tid);
    const float inv = 1.f / s;
#pragma unroll
    for (int i = 0; i < 8; i++) p[tid + i * 256] = v[i] * inv;
}

// LayerNorm in place on d_out — one block per row of 1024.
__global__ __launch_bounds__(256, 4)
void ln_k(float* __restrict__ out, const float* __restrict__ gamma,
          const float* __restrict__ beta)
{
    __shared__ float sred[8];
    float* p = out + (size_t)blockIdx.x * D;
    const int tid = threadIdx.x;
    float4 v = *(const float4*)&p[tid * 4];
    float s = v.x + v.y + v.z + v.w;
    s = blk_sum(s, sred, tid);
    const float mu = s * (1.f / D);
    const float dx = v.x - mu, dy = v.y - mu, dz = v.z - mu, dw = v.w - mu;
    float ssq = dx * dx + dy * dy + dz * dz + dw * dw;
    ssq = blk_sum(ssq, sred, tid);
    const float rs = rsqrtf(ssq * (1.f / D) + 1e-5f);
    float4 g  = *(const float4*)&gamma[tid * 4];
    float4 be = *(const float4*)&beta[tid * 4];
    float4 o;
    o.x = g.x * dx * rs + be.x;
    o.y = g.y * dy * rs + be.y;
    o.z = g.z * dz * rs + be.z;
    o.w = g.w * dw * rs + be.w;
    *(float4*)&p[tid * 4] = o;
}

// ---------------------------------------------------------------------------
extern "C" void kernel_launch(void* const* d_in, const int* in_sizes, int n_in,
                              void* d_out, int out_size)
{
    (void)in_sizes; (void)n_in; (void)out_size;
    const float* x       = (const float*)d_in[0];
    const float* memory  = (const float*)d_in[1];
    const float* pos_emb = (const float*)d_in[2];
    const float* pbu     = (const float*)d_in[3];
    const float* pbv     = (const float*)d_in[4];
    const float* W_qkv   = (const float*)d_in[5];
    const float* W_rel   = (const float*)d_in[6];
    const float* W_o     = (const float*)d_in[7];
    const float* gamma   = (const float*)d_in[8];
    const float* beta    = (const float*)d_in[9];
    float* out = (float*)d_out;

    // 1) QKV projection: [8192 x 3072 x 1024], scatter q/k/v
    gemm_nt<0><<<dim3(N3 / 128, (T * B) / 128, 1), 256>>>(
        memory, x, W_qkv, nullptr, nullptr, nullptr, T * B, N3, D);
    // 2) Positional projection: [8192 x 1024 x 1024] -> g_r
    gemm_nt<1><<<dim3(D / 128, (T * B) / 128, 1), 256>>>(
        pos_emb, nullptr, W_rel, nullptr, nullptr, nullptr, T * B, D, D);
    // 3) raw BD = (Q+v) @ R^T per (b,n): [1024 x 2048 x 64] x 64
    gemm_nt<2><<<dim3(T / 128, S / 128, B * NH), 256>>>(
        nullptr, nullptr, nullptr, pbv, nullptr, nullptr, S, T, HD);
    // 4) scores = scale*((Q+u)@K^T + shifted BD) per (b,n)
    gemm_nt<3><<<dim3(T / 128, S / 128, B * NH), 256>>>(
        nullptr, nullptr, nullptr, pbu, nullptr, nullptr, S, T, HD);
    // 5) softmax over keys
    softmax_k<<<B * NH * S, 256>>>();
    // 6) attn_vec = P @ V per (b,n): [1024 x 64 x 2048] x 64
    gemm_pv<<<dim3(1, S / 128, B * NH), 256>>>();
    // 7) out-proj + residual: [4096 x 1024 x 1024]
    gemm_nt<5><<<dim3(D / 128, (S * B) / 128, 1), 256>>>(
        nullptr, nullptr, W_o, nullptr, x, out, S * B, D, D);
    // 8) LayerNorm in place
    ln_k<<<S * B, 256>>>(out, gamma, beta);
}

// round 17
// speedup vs baseline: 1.4368x; 1.4368x over previous
#include <cuda_runtime.h>
#include <cuda_bf16.h>

// ---------------------------------------------------------------------------
// Transformer-XL relative MHA + residual + LayerNorm (fp32 accuracy via
// bf16 hi/lo split MMAs; split numerics validated in R6: rel_err 1.9e-6).
//
// Pipeline: QKV/REL/BDraw projections as NT GEMMs (smem-staged coalesced
// epilogues); scores+softmax+PV fused into one flash-attention kernel
// (g_sc eliminated); out-proj + LN.
//
// rel_shift closed form, e = j - i + 1023:
//   e <  2048 : BD(i,j) = raw[i, e]
//   e == 2048 : BD(i,j) = 0
//   e >  2048 : BD(i,j) = raw[i+1, e-2049]   (wrap; i <= 1021 so in-bounds)
// Flat identity: (i+1)*T + (e-T-1) == i*T + e - 1 -> each BD row is a
// contiguous segment with one inserted zero (coalesced staging in flash).
// NOTE: the wrap path reads the lower-left triangle of raw (c < 1023-i), so
// EVERY entry of raw is live -- no tile of mode-2 may be skipped.
// ---------------------------------------------------------------------------

namespace {
constexpr int S    = 1024;
constexpr int MEMN = 1024;
constexpr int T    = 2048;
constexpr int B    = 4;
constexpr int D    = 1024;
constexpr int NH   = 16;
constexpr int HD   = 64;
constexpr int N3   = 3072;
}

__device__ float g_q [(size_t)B * NH * S * HD];   //  16 MB [b][n][i][d]
__device__ float g_k [(size_t)B * NH * T * HD];   //  32 MB [b][n][t][d]
__device__ float g_v [(size_t)B * NH * T * HD];   //  32 MB
__device__ float g_r [(size_t)B * NH * T * HD];   //  32 MB
__device__ float g_bd[(size_t)B * NH * S * T];    // 512 MB raw BD
__device__ float g_av[(size_t)S * B * D];         //  16 MB attn_vec [i][b][h]

__device__ __forceinline__ void mma16816(float* c, const unsigned* a, const unsigned* b)
{
    asm volatile(
        "mma.sync.aligned.m16n8k16.row.col.f32.bf16.bf16.f32 "
        "{%0,%1,%2,%3}, {%4,%5,%6,%7}, {%8,%9}, {%0,%1,%2,%3};\n"
        : "+f"(c[0]), "+f"(c[1]), "+f"(c[2]), "+f"(c[3])
        : "r"(a[0]), "r"(a[1]), "r"(a[2]), "r"(a[3]), "r"(b[0]), "r"(b[1]));
}

__device__ __forceinline__ void split2(float v0, float v1,
                                       __nv_bfloat162& h2, __nv_bfloat162& l2)
{
    h2 = __floats2bfloat162_rn(v0, v1);
    l2 = __floats2bfloat162_rn(v0 - __bfloat162float(h2.x),
                               v1 - __bfloat162float(h2.y));
}

// ---------------------------------------------------------------------------
// Generic NT GEMM.  128x128 tile, BK=16 (padded stride 24), 256 threads,
// 2 CTA/SM, double-buffered.  Epilogue staged through smem for coalesced
// float4 stores.
// MODE 0: QKV projection; MODE 1: REL projection; MODE 2: BDraw -> g_bd;
// MODE 5: out-proj + residual -> d_out
// ---------------------------------------------------------------------------
template <int MODE>
__global__ __launch_bounds__(256, 2)
void gemm_nt(const float* __restrict__ Aa, const float* __restrict__ Ab,
             const float* __restrict__ Bm, const float* __restrict__ biasbase,
             const float* __restrict__ aux, float* __restrict__ Cout,
             int M, int N, int K)
{
    constexpr int BM = 128, BNT = 128, BK = 16, BKP = 24;
    constexpr int STS_ = 132;                       // stage row stride (floats)
    __shared__ alignas(16) char smraw[2 * BM * BKP * 2 * 2 + 2 * BNT * BKP * 2 * 2];
    __nv_bfloat16* sAh = (__nv_bfloat16*)smraw;     // [2][BM][BKP]
    __nv_bfloat16* sAl = sAh + 2 * BM * BKP;
    __nv_bfloat16* sBh = sAl + 2 * BM * BKP;
    __nv_bfloat16* sBl = sBh + 2 * BNT * BKP;
    float* stage = (float*)smraw;                   // [64][STS_] (33792 B)

    const int tid  = threadIdx.x;
    const int m0   = blockIdx.y * BM;
    const int n0   = blockIdx.x * BNT;
    const int z    = blockIdx.z;
    const int warp = tid >> 5;
    const int lane = tid & 31;
    const int g    = lane >> 2;
    const int tig  = lane & 3;
    const int wm0  = (warp >> 2) * 64;
    const int wn0  = (warp & 3) * 32;

    if constexpr (MODE == 0) {
        if (blockIdx.x < 8 && blockIdx.y < 32) return;   // dead q-for-memory tiles
    }

    const float* bias = nullptr;
    if constexpr (MODE == 2) bias = biasbase + (z & 15) * HD;

    float acc[4][4][4];
#pragma unroll
    for (int i = 0; i < 4; i++)
#pragma unroll
        for (int j = 0; j < 4; j++)
#pragma unroll
            for (int c = 0; c < 4; c++) acc[i][j][c] = 0.f;

    float4 pa[2], pb[2];

    auto loadA = [&](int k0) {
#pragma unroll
        for (int it = 0; it < 2; it++) {
            int idx  = tid * 2 + it;
            int row  = idx >> 2;
            int ks   = (idx & 3) << 2;
            int mrow = m0 + row;
            const float* ap;
            if constexpr (MODE == 0)
                ap = (mrow < MEMN * B) ? Aa + (size_t)mrow * D
                                       : Ab + (size_t)(mrow - MEMN * B) * D;
            else if constexpr (MODE == 1)
                ap = Aa + (size_t)mrow * D;
            else if constexpr (MODE == 2)
                ap = g_q + ((size_t)z * S + mrow) * HD;
            else
                ap = g_av + (size_t)mrow * D;
            float4 v = *(const float4*)(ap + k0 + ks);
            if constexpr (MODE == 2) {
                v.x += bias[k0 + ks + 0];
                v.y += bias[k0 + ks + 1];
                v.z += bias[k0 + ks + 2];
                v.w += bias[k0 + ks + 3];
            }
            pa[it] = v;
        }
    };
    auto loadB = [&](int k0) {
#pragma unroll
        for (int it = 0; it < 2; it++) {
            int idx  = tid * 2 + it;
            int row  = idx >> 2;
            int ks   = (idx & 3) << 2;
            int nrow = n0 + row;
            const float* bp;
            if constexpr (MODE == 2)
                bp = g_r + ((size_t)z * T + nrow) * HD;
            else
                bp = Bm + (size_t)nrow * K;
            pb[it] = *(const float4*)(bp + k0 + ks);
        }
    };
    auto stash = [&](int buf) {
#pragma unroll
        for (int it = 0; it < 2; it++) {
            int idx = tid * 2 + it;
            int row = idx >> 2;
            int ks  = (idx & 3) << 2;
            const float av[4] = { pa[it].x, pa[it].y, pa[it].z, pa[it].w };
            const float bv[4] = { pb[it].x, pb[it].y, pb[it].z, pb[it].w };
#pragma unroll
            for (int e = 0; e < 4; e += 2) {
                __nv_bfloat162 h2, l2;
                split2(av[e], av[e + 1], h2, l2);
                *(__nv_bfloat162*)&sAh[(buf * BM + row) * BKP + ks + e] = h2;
                *(__nv_bfloat162*)&sAl[(buf * BM + row) * BKP + ks + e] = l2;
                split2(bv[e], bv[e + 1], h2, l2);
                *(__nv_bfloat162*)&sBh[(buf * BNT + row) * BKP + ks + e] = h2;
                *(__nv_bfloat162*)&sBl[(buf * BNT + row) * BKP + ks + e] = l2;
            }
        }
    };

    auto ldAfrag = [&](unsigned A[4][4], const __nv_bfloat16* src) {
#pragma unroll
        for (int mf = 0; mf < 4; mf++) {
            int r = wm0 + mf * 16 + g;
            A[mf][0] = *(const unsigned*)&src[r * BKP + tig * 2    ];
            A[mf][1] = *(const unsigned*)&src[(r + 8) * BKP + tig * 2    ];
            A[mf][2] = *(const unsigned*)&src[r * BKP + tig * 2 + 8];
            A[mf][3] = *(const unsigned*)&src[(r + 8) * BKP + tig * 2 + 8];
        }
    };
    auto ldBfrag = [&](unsigned Bf[4][2], const __nv_bfloat16* src) {
#pragma unroll
        for (int nf = 0; nf < 4; nf++) {
            int r = wn0 + nf * 8 + g;
            Bf[nf][0] = *(const unsigned*)&src[r * BKP + tig * 2    ];
            Bf[nf][1] = *(const unsigned*)&src[r * BKP + tig * 2 + 8];
        }
    };
    auto domma = [&](const unsigned A[4][4], const unsigned Bf[4][2]) {
#pragma unroll
        for (int mf = 0; mf < 4; mf++)
#pragma unroll
            for (int nf = 0; nf < 4; nf++)
                mma16816(acc[mf][nf], A[mf], Bf[nf]);
    };

    loadA(0); loadB(0);
    stash(0);
    __syncthreads();

    int cur = 0;
    for (int k0 = 0; k0 < K; k0 += BK) {
        const bool has_next = (k0 + BK) < K;
        if (has_next) { loadA(k0 + BK); loadB(k0 + BK); }

        unsigned Af[4][4], Bf[4][2];
        ldAfrag(Af, sAh + cur * BM * BKP);
        ldBfrag(Bf, sBl + cur * BNT * BKP);
        domma(Af, Bf);                   // hi*lo
        ldBfrag(Bf, sBh + cur * BNT * BKP);
        domma(Af, Bf);                   // hi*hi
        ldAfrag(Af, sAl + cur * BM * BKP);
        domma(Af, Bf);                   // lo*hi (B hi still live)

        if (has_next) {
            stash(cur ^ 1);
            __syncthreads();
            cur ^= 1;
        }
    }

    // ---- staged epilogue: 2 rounds of 64x128, coalesced float4 stores ----
    __syncthreads();                      // mainloop smem reads done
#pragma unroll
    for (int r = 0; r < 2; r++) {
        if ((warp >> 2) == r) {
#pragma unroll
            for (int mf = 0; mf < 4; mf++)
#pragma unroll
                for (int nf = 0; nf < 4; nf++)
#pragma unroll
                    for (int ci = 0; ci < 4; ci++) {
                        int mloc = mf * 16 + g + ((ci >> 1) << 3);      // 0..63
                        int hloc = wn0 + nf * 8 + tig * 2 + (ci & 1);   // 0..127
                        stage[mloc * STS_ + hloc] = acc[mf][nf][ci];
                    }
        }
        __syncthreads();
#pragma unroll
        for (int c = 0; c < 8; c++) {
            int chunk = c * 256 + tid;        // 0..2047 float4 chunks
            int mloc  = chunk >> 5;           // 0..63
            int col4  = (chunk & 31) << 2;    // 0..124
            float4 v = *(const float4*)&stage[mloc * STS_ + col4];
            int m = m0 + r * 64 + mloc;
            int h = n0 + col4;
            if constexpr (MODE == 0) {
                int t  = m >> 2, bb = m & 3;
                int sec = h >> 10, hh = h & 1023;
                int n  = hh >> 6, dd = hh & 63;
                if (sec == 0) {
                    if (t >= MEMN)
                        *(float4*)&g_q[(((size_t)bb * NH + n) * S + (t - MEMN)) * HD + dd] = v;
                } else if (sec == 1) {
                    *(float4*)&g_k[(((size_t)bb * NH + n) * T + t) * HD + dd] = v;
                } else {
                    *(float4*)&g_v[(((size_t)bb * NH + n) * T + t) * HD + dd] = v;
                }
            } else if constexpr (MODE == 1) {
                int t = m >> 2, bb = m & 3;
                int n = h >> 6, dd = h & 63;
                *(float4*)&g_r[(((size_t)bb * NH + n) * T + t) * HD + dd] = v;
            } else if constexpr (MODE == 2) {
                *(float4*)&g_bd[((size_t)z * S + m) * T + h] = v;
            } else { // MODE 5: out-proj + residual
                const float4 a = *(const float4*)&aux[(size_t)m * D + h];
                v.x += a.x; v.y += a.y; v.z += a.z; v.w += a.w;
                *(float4*)&Cout[(size_t)m * D + h] = v;
            }
        }
        if (r == 0) __syncthreads();      // round-1 staging overwrites
    }
}

// ---------------------------------------------------------------------------
// Fused flash attention: scores (AC + shifted BD) + online softmax + P@V.
// Grid (S/128, 64).  256 threads = 8 warps; warp w owns query rows w*16..+15.
// Key tiles of 64.  BD tile staged coalesced into smem (stride 76 floats),
// with its long-latency scalar LDGs issued FIRST so they overlap the K/V
// loads and split-convert arithmetic (MLP front-batching).
// All MMAs bf16 hi/lo split.
// ---------------------------------------------------------------------------
__global__ __launch_bounds__(256, 2)
void flash_attn(const float* __restrict__ pbu)
{
    constexpr int QT = 128, KT = 64, PAD = 72, BDS = 76;
    extern __shared__ __nv_bfloat16 dyn[];
    __nv_bfloat16* qh = dyn;                 // [QT][PAD]
    __nv_bfloat16* ql = qh + QT * PAD;
    __nv_bfloat16* kh = ql + QT * PAD;       // [KT][PAD]
    __nv_bfloat16* kl = kh + KT * PAD;
    __nv_bfloat16* vh = kl + KT * PAD;       // [HD][PAD]  (V transposed: [dd][j])
    __nv_bfloat16* vl = vh + HD * PAD;
    float* bdt = (float*)(vl + HD * PAD);    // [QT][BDS]  staged BD tile

    const int tid  = threadIdx.x;
    const int m0   = blockIdx.x * QT;
    const int z    = blockIdx.y;             // b*16 + n
    const int warp = tid >> 5;
    const int lane = tid & 31;
    const int g    = lane >> 2;
    const int tig  = lane & 3;
    const int wr0  = warp * 16;
    const int bb   = z >> 4, n = z & 15;

    const float* Qp = g_q + ((size_t)z * S + m0) * HD;
    const float* Kp = g_k + (size_t)z * T * HD;
    const float* Vp = g_v + (size_t)z * T * HD;
    const float* BDp = g_bd + (size_t)z * S * T;
    const float* up = pbu + n * HD;

    // ---- load Q + u tile (128 x 64), split hi/lo ----
#pragma unroll
    for (int it = 0; it < 8; it++) {
        int idx = it * 256 + tid;            // 0..2047 float4 slots
        int row = idx >> 4;
        int k4  = (idx & 15) << 2;
        float4 v = *(const float4*)(Qp + (size_t)row * HD + k4);
        v.x += up[k4 + 0]; v.y += up[k4 + 1];
        v.z += up[k4 + 2]; v.w += up[k4 + 3];
        __nv_bfloat162 h2, l2;
        split2(v.x, v.y, h2, l2);
        *(__nv_bfloat162*)&qh[row * PAD + k4    ] = h2;
        *(__nv_bfloat162*)&ql[row * PAD + k4    ] = l2;
        split2(v.z, v.w, h2, l2);
        *(__nv_bfloat162*)&qh[row * PAD + k4 + 2] = h2;
        *(__nv_bfloat162*)&ql[row * PAD + k4 + 2] = l2;
    }

    float mrow[2] = { -1e30f, -1e30f };
    float lrow[2] = { 0.f, 0.f };
    float oacc[8][4];
#pragma unroll
    for (int i = 0; i < 8; i++)
#pragma unroll
        for (int c = 0; c < 4; c++) oacc[i][c] = 0.f;

    auto ldA = [&](unsigned A[4], const __nv_bfloat16* src, int kc) {
        const __nv_bfloat16* p = src + (wr0 + g) * PAD + kc * 16 + tig * 2;
        A[0] = *(const unsigned*)p;
        A[1] = *(const unsigned*)(p + 8 * PAD);
        A[2] = *(const unsigned*)(p + 8);
        A[3] = *(const unsigned*)(p + 8 * PAD + 8);
    };
    auto ldB = [&](unsigned Bf[2], const __nv_bfloat16* src, int nf, int kc) {
        const __nv_bfloat16* p = src + (nf * 8 + g) * PAD + kc * 16 + tig * 2;
        Bf[0] = *(const unsigned*)p;
        Bf[1] = *(const unsigned*)(p + 8);
    };

    for (int jt = 0; jt < T / KT; jt++) {
        const int j0 = jt * KT;
        __syncthreads();                     // protect previous-iter smem reads
        // ---- stage BD tile first: long-latency scalar LDGs get max MLP ----
#pragma unroll
        for (int it = 0; it < 32; it++) {
            int idx = it * 256 + tid;        // 8192 = 128 rows x 64 cols
            int ir  = idx >> 6;
            int jc  = idx & 63;
            int i   = m0 + ir;
            int e   = j0 + jc - i + (S - 1);
            float v;
            if (e == T)      v = 0.f;
            else             v = BDp[(size_t)i * T + ((e > T) ? (e - 1) : e)];
            bdt[ir * BDS + jc] = v;
        }
        // ---- load K tile + V tile (transposed), split hi/lo ----
#pragma unroll
        for (int it = 0; it < 4; it++) {
            int idx = it * 256 + tid;        // 0..1023 float4 slots
            int row = idx >> 4;              // 0..63 (j within tile)
            int k4  = (idx & 15) << 2;
            float4 kv = *(const float4*)(Kp + (size_t)(j0 + row) * HD + k4);
            __nv_bfloat162 h2, l2;
            split2(kv.x, kv.y, h2, l2);
            *(__nv_bfloat162*)&kh[row * PAD + k4    ] = h2;
            *(__nv_bfloat162*)&kl[row * PAD + k4    ] = l2;
            split2(kv.z, kv.w, h2, l2);
            *(__nv_bfloat162*)&kh[row * PAD + k4 + 2] = h2;
            *(__nv_bfloat162*)&kl[row * PAD + k4 + 2] = l2;
            float4 vv = *(const float4*)(Vp + (size_t)(j0 + row) * HD + k4);
            const float bv[4] = { vv.x, vv.y, vv.z, vv.w };
#pragma unroll
            for (int e = 0; e < 4; e++) {    // transpose: vt[dd][j]
                __nv_bfloat16 h = __float2bfloat16(bv[e]);
                __nv_bfloat16 l = __float2bfloat16(bv[e] - __bfloat162float(h));
                vh[(k4 + e) * PAD + row] = h;
                vl[(k4 + e) * PAD + row] = l;
            }
        }
        __syncthreads();

        // ---- S = (Q+u) K^T  (per warp: 16 x 64) ----
        float sacc[8][4];
#pragma unroll
        for (int i = 0; i < 8; i++)
#pragma unroll
            for (int c = 0; c < 4; c++) sacc[i][c] = 0.f;
#pragma unroll
        for (int kc = 0; kc < 4; kc++) {
            unsigned Ah[4], Al[4], Bf[2];
            ldA(Ah, qh, kc);
            ldA(Al, ql, kc);
#pragma unroll
            for (int nf = 0; nf < 8; nf++) {
                ldB(Bf, kl, nf, kc); mma16816(sacc[nf], Ah, Bf);   // hi*lo
                ldB(Bf, kh, nf, kc); mma16816(sacc[nf], Ah, Bf);   // hi*hi
                mma16816(sacc[nf], Al, Bf);                        // lo*hi
            }
        }

        // ---- add staged BD (conflict-free diagonal read), scale ----
#pragma unroll
        for (int nf = 0; nf < 8; nf++)
#pragma unroll
            for (int ci = 0; ci < 4; ci++) {
                int ir = wr0 + g + ((ci >> 1) << 3);
                int jc = nf * 8 + tig * 2 + (ci & 1);
                sacc[nf][ci] = (sacc[nf][ci] + bdt[ir * BDS + jc]) * 0.125f;
            }

        // ---- online softmax over this key tile ----
        float tmax[2] = { -1e30f, -1e30f };
#pragma unroll
        for (int nf = 0; nf < 8; nf++)
#pragma unroll
            for (int ci = 0; ci < 4; ci++)
                tmax[ci >> 1] = fmaxf(tmax[ci >> 1], sacc[nf][ci]);
#pragma unroll
        for (int h = 0; h < 2; h++) {
            tmax[h] = fmaxf(tmax[h], __shfl_xor_sync(0xffffffffu, tmax[h], 1));
            tmax[h] = fmaxf(tmax[h], __shfl_xor_sync(0xffffffffu, tmax[h], 2));
        }
        float al[2];
#pragma unroll
        for (int h = 0; h < 2; h++) {
            float mn = fmaxf(mrow[h], tmax[h]);
            al[h] = __expf(mrow[h] - mn);
            mrow[h] = mn;
        }
        float tsum[2] = { 0.f, 0.f };
#pragma unroll
        for (int nf = 0; nf < 8; nf++)
#pragma unroll
            for (int ci = 0; ci < 4; ci++) {
                float p = __expf(sacc[nf][ci] - mrow[ci >> 1]);
                sacc[nf][ci] = p;
                tsum[ci >> 1] += p;
            }
#pragma unroll
        for (int h = 0; h < 2; h++) {
            tsum[h] += __shfl_xor_sync(0xffffffffu, tsum[h], 1);
            tsum[h] += __shfl_xor_sync(0xffffffffu, tsum[h], 2);
            lrow[h] = lrow[h] * al[h] + tsum[h];
        }
#pragma unroll
        for (int nf = 0; nf < 8; nf++)
#pragma unroll
            for (int ci = 0; ci < 4; ci++)
                oacc[nf][ci] *= al[ci >> 1];

        // ---- O += P @ V  (P from registers; hi/lo split) ----
#pragma unroll
        for (int kc = 0; kc < 4; kc++) {
            unsigned Ph[4], Pl[4];
#pragma unroll
            for (int q = 0; q < 4; q++) {
                int nf2 = 2 * kc + (q >> 1);
                int cb  = (q & 1) * 2;
                __nv_bfloat162 h2, l2;
                split2(sacc[nf2][cb], sacc[nf2][cb + 1], h2, l2);
                Ph[q] = *(unsigned*)&h2;
                Pl[q] = *(unsigned*)&l2;
            }
            unsigned Bf[2];
#pragma unroll
            for (int nf = 0; nf < 8; nf++) {
                ldB(Bf, vl, nf, kc); mma16816(oacc[nf], Ph, Bf);   // hi*lo
                ldB(Bf, vh, nf, kc); mma16816(oacc[nf], Ph, Bf);   // hi*hi
                mma16816(oacc[nf], Pl, Bf);                        // lo*hi
            }
        }
    }

    // ---- epilogue: O / l -> g_av ----
    float inv[2] = { 1.f / lrow[0], 1.f / lrow[1] };
#pragma unroll
    for (int nf = 0; nf < 8; nf++)
#pragma unroll
        for (int ci = 0; ci < 4; ci++) {
            int i  = m0 + wr0 + g + ((ci >> 1) << 3);
            int dd = nf * 8 + tig * 2 + (ci & 1);
            g_av[((size_t)i * B + bb) * D + n * HD + dd] = oacc[nf][ci] * inv[ci >> 1];
        }
}

// ---------------------------------------------------------------------------
__device__ __forceinline__ float blk_sum(float v, float* sred, int tid)
{
#pragma unroll
    for (int o = 16; o; o >>= 1) v += __shfl_xor_sync(0xffffffffu, v, o);
    if ((tid & 31) == 0) sred[tid >> 5] = v;
    __syncthreads();
    float r = 0.f;
#pragma unroll
    for (int w = 0; w < 8; w++) r += sred[w];
    __syncthreads();
    return r;
}

// LayerNorm in place on d_out — one block per row of 1024.
__global__ __launch_bounds__(256, 4)
void ln_k(float* __restrict__ out, const float* __restrict__ gamma,
          const float* __restrict__ beta)
{
    __shared__ float sred[8];
    float* p = out + (size_t)blockIdx.x * D;
    const int tid = threadIdx.x;
    float4 v = *(const float4*)&p[tid * 4];
    float s = v.x + v.y + v.z + v.w;
    s = blk_sum(s, sred, tid);
    const float mu = s * (1.f / D);
    const float dx = v.x - mu, dy = v.y - mu, dz = v.z - mu, dw = v.w - mu;
    float ssq = dx * dx + dy * dy + dz * dz + dw * dw;
    ssq = blk_sum(ssq, sred, tid);
    const float rs = rsqrtf(ssq * (1.f / D) + 1e-5f);
    float4 g  = *(const float4*)&gamma[tid * 4];
    float4 be = *(const float4*)&beta[tid * 4];
    float4 o;
    o.x = g.x * dx * rs + be.x;
    o.y = g.y * dy * rs + be.y;
    o.z = g.z * dz * rs + be.z;
    o.w = g.w * dw * rs + be.w;
    *(float4*)&p[tid * 4] = o;
}

// ---------------------------------------------------------------------------
extern "C" void kernel_launch(void* const* d_in, const int* in_sizes, int n_in,
                              void* d_out, int out_size)
{
    (void)in_sizes; (void)n_in; (void)out_size;
    const float* x       = (const float*)d_in[0];
    const float* memory  = (const float*)d_in[1];
    const float* pos_emb = (const float*)d_in[2];
    const float* pbu     = (const float*)d_in[3];
    const float* pbv     = (const float*)d_in[4];
    const float* W_qkv   = (const float*)d_in[5];
    const float* W_rel   = (const float*)d_in[6];
    const float* W_o     = (const float*)d_in[7];
    const float* gamma   = (const float*)d_in[8];
    const float* beta    = (const float*)d_in[9];
    float* out = (float*)d_out;

    // bf16 tiles 73728 B + BD tile 128*76*4 = 38912 B
    constexpr int FLASH_SMEM = 73728 + 38912;          // 112640 B
    cudaFuncSetAttribute(flash_attn, cudaFuncAttributeMaxDynamicSharedMemorySize,
                         FLASH_SMEM);

    // 1) QKV projection
    gemm_nt<0><<<dim3(N3 / 128, (T * B) / 128, 1), 256>>>(
        memory, x, W_qkv, nullptr, nullptr, nullptr, T * B, N3, D);
    // 2) Positional projection -> g_r
    gemm_nt<1><<<dim3(D / 128, (T * B) / 128, 1), 256>>>(
        pos_emb, nullptr, W_rel, nullptr, nullptr, nullptr, T * B, D, D);
    // 3) raw BD = (Q+v) @ R^T per (b,n) -> g_bd
    gemm_nt<2><<<dim3(T / 128, S / 128, B * NH), 256>>>(
        nullptr, nullptr, nullptr, pbv, nullptr, nullptr, S, T, HD);
    // 4) fused scores + softmax + PV -> g_av
    flash_attn<<<dim3(S / 128, B * NH), 256, FLASH_SMEM>>>(pbu);
    // 5) out-proj + residual
    gemm_nt<5><<<dim3(D / 128, (S * B) / 128, 1), 256>>>(
        nullptr, nullptr, W_o, nullptr, x, out, S * B, D, D);
    // 6) LayerNorm in place
    ln_k<<<S * B, 256>>>(out, gamma, beta);
}